// round 9
// baseline (speedup 1.0000x reference)
#include <cuda_runtime.h>
#include <cuda_bf16.h>
#include <cstdint>
#include <cstddef>
#include <math.h>

#define NTOK 8192
#define Hd 2048
#define Id 1024
#define Pd 4096
#define Dd 1024

// ---------------- static device scratch ----------------
__device__ __nv_bfloat16 g_xa0[(size_t)NTOK * Hd];
__device__ __nv_bfloat16 g_xa1[(size_t)NTOK * Hd];
__device__ __nv_bfloat16 g_w1t0[(size_t)Id * Hd];
__device__ __nv_bfloat16 g_w1t1[(size_t)Id * Hd];
__device__ __nv_bfloat16 g_i0[(size_t)NTOK * Id];
__device__ __nv_bfloat16 g_w2t0[(size_t)Pd * Id];
__device__ float         g_w2tf[(size_t)Pd * Id];
__device__ __nv_bfloat16 g_wpt0[(size_t)Dd * Hd];
__device__ __nv_bfloat16 g_wpt1[(size_t)Dd * Hd];
__device__ __nv_bfloat16 g_ca0[(size_t)NTOK * 2 * Dd];
__device__ __nv_bfloat16 g_ca1[(size_t)NTOK * 2 * Dd];
__device__ __nv_bfloat16 g_wmt0[(size_t)Dd * 2 * Dd];
__device__ __nv_bfloat16 g_wmt1[(size_t)Dd * 2 * Dd];
__device__ __nv_bfloat16 g_lb[(size_t)NTOK * Pd];      // bf16 logits
__device__ float         g_inter[(size_t)NTOK * Id];
__device__ float         g_proj[(size_t)NTOK * Dd];
__device__ float         g_usage[Pd];

__device__ __forceinline__ __nv_bfloat16* bufselw(int s) {
    switch (s) {
        case 0:  return g_xa0;  case 1:  return g_xa1;
        case 3:  return g_w1t0; case 4:  return g_w1t1;
        case 6:  return g_i0;   case 7:  return g_w2t0;
        case 8:  return g_wpt0; case 9:  return g_wpt1;
        case 10: return g_ca0;  case 11: return g_ca1;
        case 12: return g_wmt0; default: return g_wmt1;
    }
}
__device__ __forceinline__ const __nv_bfloat16* bufsel(int s) { return bufselw(s); }
__device__ __forceinline__ float* csel(int s, float* ext) {
    switch (s) {
        case 0: return g_inter;
        case 2: return g_proj;
        default: return ext;
    }
}

// ---------------- PTX helpers ----------------
__device__ __forceinline__ uint32_t smem_u32(const void* p) {
    uint32_t a;
    asm("{ .reg .u64 t; cvta.to.shared.u64 t, %1; cvt.u32.u64 %0, t; }" : "=r"(a) : "l"(p));
    return a;
}
#define CPA16(d, s) asm volatile("cp.async.cg.shared.global [%0], [%1], 16;" :: "r"(d), "l"(s) : "memory")
#define CPA_COMMIT() asm volatile("cp.async.commit_group;" ::: "memory")
#define CPA_WAIT0() asm volatile("cp.async.wait_group 0;" ::: "memory")

__device__ __forceinline__ void ldmx4(uint32_t* r, uint32_t addr) {
    asm volatile("ldmatrix.sync.aligned.m8n8.x4.shared.b16 {%0,%1,%2,%3}, [%4];"
                 : "=r"(r[0]), "=r"(r[1]), "=r"(r[2]), "=r"(r[3]) : "r"(addr));
}
__device__ __forceinline__ void mma16816(float* d, const uint32_t* a, const uint32_t* b) {
    asm volatile("mma.sync.aligned.m16n8k16.row.col.f32.bf16.bf16.f32 "
                 "{%0,%1,%2,%3}, {%4,%5,%6,%7}, {%8,%9}, {%0,%1,%2,%3};"
                 : "+f"(d[0]), "+f"(d[1]), "+f"(d[2]), "+f"(d[3])
                 : "r"(a[0]), "r"(a[1]), "r"(a[2]), "r"(a[3]), "r"(b[0]), "r"(b[1]));
}

// ---------------- HMMA GEMM: D[M,N] = sum_p A_p @ B_p^T + bias --------------
// Tile 128(M) x 256(N), BK=32, 2-stage static smem (A 8KB + B 16KB per stage).
#define STAGE_B 24576

__device__ __forceinline__ uint32_t swzo(int row, int kcol) {
    return (uint32_t)(row * 64 + ((((kcol >> 3) ^ ((row >> 1) & 3)) << 4)) + ((kcol & 7) << 1));
}

__global__ void __launch_bounds__(256)
gemm_mma(uint32_t aPack, uint32_t bPack, int npass, int K,
         const float* __restrict__ bias, float* Cext, int cselv, int ldc,
         int relu, int conv)   // conv: 0 none, 1 also bf16->g_i0, 2 bf16 ONLY ->g_lb
{
    __shared__ __align__(1024) char smem[2 * STAGE_B];
    const uint32_t sb = smem_u32(smem);
    const int tid = threadIdx.x, lane = tid & 31, wid = tid >> 5;
    const int wm = wid & 1, wn = wid >> 1;          // warp grid 2(M) x 4(N), 64x64 each
    const int bn = blockIdx.x, bm = blockIdx.y;
    float* C = csel(cselv, Cext);

    const int kcp = K >> 5;
    const int NCH = npass * kcp;

    float acc[4][8][4];
    #pragma unroll
    for (int i = 0; i < 4; i++)
        #pragma unroll
        for (int j = 0; j < 8; j++)
            #pragma unroll
            for (int q = 0; q < 4; q++) acc[i][j][q] = 0.0f;

    auto load_chunk = [&](int ch, int buf) {
        const int p = ch / kcp, kc = ch % kcp;
        const __nv_bfloat16* A = bufsel((aPack >> (4 * p)) & 15) + (size_t)(bm * 128) * K + kc * 32;
        const __nv_bfloat16* B = bufsel((bPack >> (4 * p)) & 15) + (size_t)(bn * 256) * K + kc * 32;
        const uint32_t ab = sb + buf * STAGE_B;
        const uint32_t bb = ab + 8192;
        #pragma unroll
        for (int i = 0; i < 2; i++) {          // A: 128 rows x 32 cols
            const int g = tid + i * 256, r = g >> 2, c = g & 3;
            CPA16(ab + swzo(r, c * 8), A + (size_t)r * K + c * 8);
        }
        #pragma unroll
        for (int i = 0; i < 4; i++) {          // B: 256 rows x 32 cols
            const int g = tid + i * 256, r = g >> 2, c = g & 3;
            CPA16(bb + swzo(r, c * 8), B + (size_t)r * K + c * 8);
        }
        CPA_COMMIT();
    };

    load_chunk(0, 0);

    const int a_r = wm * 64 + (lane & 15);                      // + mt*16
    const int a_kc = (lane >> 4) * 8;                           // + ks*16
    const int b_r = wn * 64 + (lane & 7) + ((lane >> 4) << 3);  // + q*16
    const int b_kc = ((lane >> 3) & 1) * 8;                     // + ks*16

    for (int c = 0; c < NCH; c++) {
        CPA_WAIT0();            // chunk c resident (only group in flight)
        __syncthreads();        // loads visible; all warps done with compute(c-1)
        if (c + 1 < NCH) load_chunk(c + 1, (c + 1) & 1);

        const uint32_t abase = sb + (c & 1) * STAGE_B;
        const uint32_t bbase = abase + 8192;
        #pragma unroll
        for (int ks = 0; ks < 2; ks++) {
            uint32_t af[4][4], bf[4][4];
            #pragma unroll
            for (int mt = 0; mt < 4; mt++)
                ldmx4(af[mt], abase + swzo(a_r + mt * 16, ks * 16 + a_kc));
            #pragma unroll
            for (int q = 0; q < 4; q++)
                ldmx4(bf[q], bbase + swzo(b_r + q * 16, ks * 16 + b_kc));
            #pragma unroll
            for (int mt = 0; mt < 4; mt++)
                #pragma unroll
                for (int nt = 0; nt < 8; nt++)
                    mma16816(acc[mt][nt], af[mt], &bf[nt >> 1][(nt & 1) * 2]);
        }
    }

    #pragma unroll
    for (int mt = 0; mt < 4; mt++) {
        const int r0 = bm * 128 + wm * 64 + mt * 16 + (lane >> 2);
        #pragma unroll
        for (int nt = 0; nt < 8; nt++) {
            const int col = bn * 256 + wn * 64 + nt * 8 + (lane & 3) * 2;
            const float bb0 = bias[col], bb1 = bias[col + 1];
            float v0 = acc[mt][nt][0] + bb0, v1 = acc[mt][nt][1] + bb1;
            float v2 = acc[mt][nt][2] + bb0, v3 = acc[mt][nt][3] + bb1;
            if (relu) {
                v0 = fmaxf(v0, 0.f); v1 = fmaxf(v1, 0.f);
                v2 = fmaxf(v2, 0.f); v3 = fmaxf(v3, 0.f);
            }
            if (conv != 2) {
                *(float2*)(C + (size_t)r0 * ldc + col) = make_float2(v0, v1);
                *(float2*)(C + (size_t)(r0 + 8) * ldc + col) = make_float2(v2, v3);
            }
            if (conv) {
                __nv_bfloat16* tb = (conv == 1) ? g_i0 : g_lb;
                *(__nv_bfloat162*)(tb + (size_t)r0 * ldc + col) =
                    __nv_bfloat162(__float2bfloat16(v0), __float2bfloat16(v1));
                *(__nv_bfloat162*)(tb + (size_t)(r0 + 8) * ldc + col) =
                    __nv_bfloat162(__float2bfloat16(v2), __float2bfloat16(v3));
            }
        }
    }
}

// ---------------- prep ----------------
__global__ void split_x2_kernel(const float* __restrict__ x) {
    size_t i = (size_t)blockIdx.x * blockDim.x + threadIdx.x;
    const size_t n = (size_t)NTOK * Hd;
    if (i >= n) return;
    float v = x[i];
    __nv_bfloat16 h0 = __float2bfloat16(v);
    g_xa0[i] = h0;
    g_xa1[i] = __float2bfloat16(v - __bfloat162float(h0));
}

__global__ void transpose_split(const float* __restrict__ W, int R, int C,
                                int s0, int s1, int wf) {
    __nv_bfloat16* T0 = bufselw(s0);
    __nv_bfloat16* T1 = (s1 >= 0) ? bufselw(s1) : nullptr;
    float* TF = wf ? g_w2tf : nullptr;

    __shared__ float t[32][33];
    const int bx = blockIdx.x * 32, by = blockIdx.y * 32;
    const int tx = threadIdx.x, ty = threadIdx.y;
    #pragma unroll
    for (int i = 0; i < 4; i++)
        t[ty + i * 8][tx] = W[(size_t)(by + ty + i * 8) * C + bx + tx];
    __syncthreads();
    #pragma unroll
    for (int i = 0; i < 4; i++) {
        const int c = bx + ty + i * 8, r = by + tx;
        const float v = t[tx][ty + i * 8];
        const size_t o = (size_t)c * R + r;
        __nv_bfloat16 h0 = __float2bfloat16(v);
        T0[o] = h0;
        if (T1) T1[o] = __float2bfloat16(v - __bfloat162float(h0));
        if (TF) TF[o] = v;
    }
}

// ---------------- reductions ----------------
template <int NT>
__device__ __forceinline__ float breduce(float v) {
    __shared__ float sh[NT];
    int tid = threadIdx.x;
    sh[tid] = v; __syncthreads();
    #pragma unroll
    for (int s = NT / 2; s > 0; s >>= 1) {
        if (tid < s) sh[tid] += sh[tid + s];
        __syncthreads();
    }
    float r = sh[0]; __syncthreads();
    return r;
}

__global__ void zero_usage_kernel() {
    int i = blockIdx.x * blockDim.x + threadIdx.x;
    if (i < Pd) g_usage[i] = 0.0f;
}

// ---------------- top-2: bf16 approx scan + exact fp32 recompute ------------
__global__ void __launch_bounds__(256)
topk_kernel(const float* __restrict__ pool, const float* __restrict__ temp_ptr,
            const float* __restrict__ b2)
{
    const int row = blockIdx.x, tid = threadIdx.x;
    const int wid = tid >> 5, lane = tid & 31;
    const __nv_bfloat16* lrow = g_lb + (size_t)row * Pd;
    float t = temp_ptr[0];
    t = fminf(fmaxf(t, 0.1f), 5.0f);
    const float it = 1.0f / t;

    float v1 = -INFINITY, v2 = -INFINITY;
    for (int j = tid * 2; j < Pd; j += 512) {
        __nv_bfloat162 p2 = *(const __nv_bfloat162*)(lrow + j);
        float va = fminf(fmaxf(__bfloat162float(p2.x) * it, -10.0f), 10.0f);
        float vb = fminf(fmaxf(__bfloat162float(p2.y) * it, -10.0f), 10.0f);
        float hi = fmaxf(va, vb), lo = fminf(va, vb);
        if (hi > v1) { v2 = fmaxf(v1, lo); v1 = hi; }
        else v2 = fmaxf(v2, hi);
    }
    __shared__ float s1[256], s2[256];
    s1[tid] = v1; s2[tid] = v2; __syncthreads();
    for (int s = 128; s > 0; s >>= 1) {
        if (tid < s) {
            float a1 = s1[tid], a2 = s2[tid], b1v = s1[tid + s], b2v = s2[tid + s];
            s1[tid] = fmaxf(a1, b1v);
            s2[tid] = fmaxf(fminf(a1, b1v), fmaxf(a2, b2v));
        }
        __syncthreads();
    }
    const float thr = s2[0] - 0.05f * it;

    __shared__ int cands[64];
    __shared__ int ncand;
    if (tid == 0) ncand = 0;
    __syncthreads();
    for (int j = tid * 2; j < Pd; j += 512) {
        __nv_bfloat162 p2 = *(const __nv_bfloat162*)(lrow + j);
        float va = fminf(fmaxf(__bfloat162float(p2.x) * it, -10.0f), 10.0f);
        float vb = fminf(fmaxf(__bfloat162float(p2.y) * it, -10.0f), 10.0f);
        if (va >= thr) { int p = atomicAdd(&ncand, 1); if (p < 64) cands[p] = j; }
        if (vb >= thr) { int p = atomicAdd(&ncand, 1); if (p < 64) cands[p] = j + 1; }
    }
    __syncthreads();
    const int nc = min(ncand, 64);

    __shared__ float exv[64];
    const float* irow = g_inter + (size_t)row * Id;
    for (int base = 0; base < nc; base += 8) {
        const int q = base + wid;
        if (q < nc) {
            const int j = cands[q];
            const float* wr = g_w2tf + (size_t)j * Id;
            float s = 0.0f;
            for (int k = lane; k < Id; k += 32) s += irow[k] * wr[k];
            #pragma unroll
            for (int o = 16; o > 0; o >>= 1) s += __shfl_down_sync(0xffffffffu, s, o);
            if (lane == 0) exv[q] = fminf(fmaxf((s + b2[j]) / t, -10.0f), 10.0f);
        }
    }
    __syncthreads();

    __shared__ float sw0, sw1;
    __shared__ int sj0, sj1;
    if (tid == 0) {
        float bv1 = -INFINITY, bv2 = -INFINITY;
        int bi1 = 0x7fffffff, bi2 = 0x7fffffff;
        for (int q = 0; q < nc; q++) {
            float v = exv[q]; int j = cands[q];
            if (v > bv1 || (v == bv1 && j < bi1)) {
                bv2 = bv1; bi2 = bi1; bv1 = v; bi1 = j;
            } else if (v > bv2 || (v == bv2 && j < bi2)) {
                bv2 = v; bi2 = j;
            }
        }
        float e = expf(bv2 - bv1), se = 1.0f + e;
        sw0 = 1.0f / se; sw1 = e / se; sj0 = bi1; sj1 = bi2;
        atomicAdd(&g_usage[bi1], sw0);
        atomicAdd(&g_usage[bi2], sw1);
    }
    __syncthreads();

    const float w0 = sw0, w1 = sw1;
    float4 a = ((const float4*)(pool + (size_t)sj0 * Dd))[tid];
    float4 b = ((const float4*)(pool + (size_t)sj1 * Dd))[tid];
    float ov[4] = { w0 * a.x + w1 * b.x, w0 * a.y + w1 * b.y,
                    w0 * a.z + w1 * b.z, w0 * a.w + w1 * b.w };
    const size_t off = (size_t)row * (2 * Dd) + Dd + tid * 4;
    #pragma unroll
    for (int q = 0; q < 4; q++) {
        __nv_bfloat16 h0 = __float2bfloat16(ov[q]);
        g_ca0[off + q] = h0;
        g_ca1[off + q] = __float2bfloat16(ov[q] - __bfloat162float(h0));
    }
}

// ---------------- layernorm -> combined[:, 0:D] splits ----------------
__global__ void __launch_bounds__(256)
ln_kernel(const float* __restrict__ gamma, const float* __restrict__ beta)
{
    const int row = blockIdx.x, tid = threadIdx.x;
    float4 v = ((const float4*)(g_proj + (size_t)row * Dd))[tid];
    float s = v.x + v.y + v.z + v.w;
    s = breduce<256>(s);
    const float mean = s * (1.0f / Dd);
    float d0 = v.x - mean, d1 = v.y - mean, d2 = v.z - mean, d3 = v.w - mean;
    float q = d0 * d0 + d1 * d1 + d2 * d2 + d3 * d3;
    q = breduce<256>(q);
    const float rs = rsqrtf(q * (1.0f / Dd) + 1e-5f);
    float4 g = ((const float4*)gamma)[tid], b = ((const float4*)beta)[tid];
    float ov[4] = { d0 * rs * g.x + b.x, d1 * rs * g.y + b.y,
                    d2 * rs * g.z + b.z, d3 * rs * g.w + b.w };
    const size_t off = (size_t)row * (2 * Dd) + tid * 4;
    #pragma unroll
    for (int k = 0; k < 4; k++) {
        __nv_bfloat16 h0 = __float2bfloat16(ov[k]);
        g_ca0[off + k] = h0;
        g_ca1[off + k] = __float2bfloat16(ov[k] - __bfloat162float(h0));
    }
}

// ---------------- diversity loss ----------------
__global__ void __launch_bounds__(512)
loss_kernel(float* __restrict__ out, int do_write)
{
    const int tid = threadIdx.x;
    float s = 0.0f;
    for (int j = tid; j < Pd; j += 512) s += g_usage[j];
    s = breduce<512>(s);
    const float denom = s + 1e-8f, uni = 1.0f / Pd;
    float q = 0.0f;
    for (int j = tid; j < Pd; j += 512) {
        float d = g_usage[j] / denom - uni;
        q += d * d;
    }
    q = breduce<512>(q);
    if (tid == 0 && do_write) out[0] = (q / Pd) * 0.01f;
}

// ---------------- launch ----------------
extern "C" void kernel_launch(void* const* d_in, const int* in_sizes, int n_in,
                              void* d_out, int out_size)
{
    const int o = (n_in >= 14) ? 1 : 0;
    const float* x     = (const float*)d_in[0];
    const float* pool  = (const float*)d_in[1];
    const float* w1    = (const float*)d_in[2 + o];
    const float* b1    = (const float*)d_in[3 + o];
    const float* w2    = (const float*)d_in[4 + o];
    const float* b2    = (const float*)d_in[5 + o];
    const float* temp  = (const float*)d_in[6 + o];
    const float* wp    = (const float*)d_in[7 + o];
    const float* bp    = (const float*)d_in[8 + o];
    const float* gamma = (const float*)d_in[9 + o];
    const float* beta  = (const float*)d_in[10 + o];
    const float* wm    = (const float*)d_in[11 + o];
    const float* bm    = (const float*)d_in[12 + o];
    float* out = (float*)d_out;

    split_x2_kernel<<<((size_t)NTOK * Hd + 255) / 256, 256>>>(x);
    transpose_split<<<dim3(Id / 32, Hd / 32), dim3(32, 8)>>>(w1, Hd, Id, 3, 4, 0);
    transpose_split<<<dim3(Pd / 32, Id / 32), dim3(32, 8)>>>(w2, Id, Pd, 7, -1, 1);
    transpose_split<<<dim3(Dd / 32, Hd / 32), dim3(32, 8)>>>(wp, Hd, Dd, 8, 9, 0);
    transpose_split<<<dim3(Dd / 32, (2 * Dd) / 32), dim3(32, 8)>>>(wm, 2 * Dd, Dd, 12, 13, 0);
    zero_usage_kernel<<<Pd / 256, 256>>>();

    // G1: inter = relu(x@w1+b1); 3-pass; fp32 + bf16 copy
    gemm_mma<<<dim3(Id / 256, NTOK / 128), 256>>>(
        0x100u, 0x343u, 3, Hd, b1, nullptr, 0, Id, 1, 1);

    // G2: logits = inter@w2+b2; 1-pass bf16 -> g_lb only
    gemm_mma<<<dim3(Pd / 256, NTOK / 128), 256>>>(
        0x6u, 0x7u, 1, Id, b2, nullptr, 9, Pd, 0, 2);

    topk_kernel<<<NTOK, 256>>>(pool, temp, b2);

    // G3: proj = x@wp+bp; 3-pass
    gemm_mma<<<dim3(Dd / 256, NTOK / 128), 256>>>(
        0x100u, 0x898u, 3, Hd, bp, nullptr, 2, Dd, 0, 0);

    ln_kernel<<<NTOK, 256>>>(gamma, beta);

    // G4: out = combined@wm+bm; 3-pass
    gemm_mma<<<dim3(Dd / 256, NTOK / 128), 256>>>(
        0xBAAu, 0xCDCu, 3, 2 * Dd, bm, out, 9, Dd, 0, 0);

    const long long tsz = (long long)NTOK * Dd;
    loss_kernel<<<1, 512>>>(out + tsz, ((long long)out_size > tsz) ? 1 : 0);
}

// round 10
// speedup vs baseline: 1.2446x; 1.2446x over previous
#include <cuda_runtime.h>
#include <cuda_bf16.h>
#include <cstdint>
#include <cstddef>
#include <math.h>

#define NTOK 8192
#define Hd 2048
#define Id 1024
#define Pd 4096
#define Dd 1024

// ---------------- static device scratch ----------------
__device__ __nv_bfloat16 g_xa0[(size_t)NTOK * Hd];
__device__ __nv_bfloat16 g_xa1[(size_t)NTOK * Hd];
__device__ __nv_bfloat16 g_w1t0[(size_t)Id * Hd];
__device__ __nv_bfloat16 g_w1t1[(size_t)Id * Hd];
__device__ __nv_bfloat16 g_i0[(size_t)NTOK * Id];
__device__ __nv_bfloat16 g_w2t0[(size_t)Pd * Id];
__device__ float         g_w2tf[(size_t)Pd * Id];
__device__ __nv_bfloat16 g_wpt0[(size_t)Dd * Hd];
__device__ __nv_bfloat16 g_wpt1[(size_t)Dd * Hd];
__device__ __nv_bfloat16 g_ca0[(size_t)NTOK * 2 * Dd];
__device__ __nv_bfloat16 g_ca1[(size_t)NTOK * 2 * Dd];
__device__ __nv_bfloat16 g_wmt0[(size_t)Dd * 2 * Dd];
__device__ __nv_bfloat16 g_wmt1[(size_t)Dd * 2 * Dd];
__device__ __nv_bfloat16 g_lb[(size_t)NTOK * Pd];      // bf16 logits
__device__ float         g_inter[(size_t)NTOK * Id];
__device__ float         g_proj[(size_t)NTOK * Dd];
__device__ float         g_usage[Pd];

__device__ __forceinline__ __nv_bfloat16* bufselw(int s) {
    switch (s) {
        case 0:  return g_xa0;  case 1:  return g_xa1;
        case 3:  return g_w1t0; case 4:  return g_w1t1;
        case 6:  return g_i0;   case 7:  return g_w2t0;
        case 8:  return g_wpt0; case 9:  return g_wpt1;
        case 10: return g_ca0;  case 11: return g_ca1;
        case 12: return g_wmt0; default: return g_wmt1;
    }
}
__device__ __forceinline__ const __nv_bfloat16* bufsel(int s) { return bufselw(s); }
__device__ __forceinline__ float* csel(int s, float* ext) {
    switch (s) {
        case 0: return g_inter;
        case 2: return g_proj;
        default: return ext;
    }
}

// ---------------- PTX helpers ----------------
__device__ __forceinline__ uint32_t smem_u32(const void* p) {
    uint32_t a;
    asm("{ .reg .u64 t; cvta.to.shared.u64 t, %1; cvt.u32.u64 %0, t; }" : "=r"(a) : "l"(p));
    return a;
}
#define CPA16(d, s) asm volatile("cp.async.cg.shared.global [%0], [%1], 16;" :: "r"(d), "l"(s) : "memory")
#define CPA_COMMIT() asm volatile("cp.async.commit_group;" ::: "memory")
#define CPA_WAIT1() asm volatile("cp.async.wait_group 1;" ::: "memory")
#define CPA_WAIT0() asm volatile("cp.async.wait_group 0;" ::: "memory")

__device__ __forceinline__ void ldmx4(uint32_t* r, uint32_t addr) {
    asm volatile("ldmatrix.sync.aligned.m8n8.x4.shared.b16 {%0,%1,%2,%3}, [%4];"
                 : "=r"(r[0]), "=r"(r[1]), "=r"(r[2]), "=r"(r[3]) : "r"(addr));
}
__device__ __forceinline__ void mma16816(float* d, const uint32_t* a, const uint32_t* b) {
    asm volatile("mma.sync.aligned.m16n8k16.row.col.f32.bf16.bf16.f32 "
                 "{%0,%1,%2,%3}, {%4,%5,%6,%7}, {%8,%9}, {%0,%1,%2,%3};"
                 : "+f"(d[0]), "+f"(d[1]), "+f"(d[2]), "+f"(d[3])
                 : "r"(a[0]), "r"(a[1]), "r"(a[2]), "r"(a[3]), "r"(b[0]), "r"(b[1]));
}

// ---------------- HMMA GEMM: D[M,N] = sum_p A_p @ B_p^T + bias --------------
// Tile 128x128, BK=32, 3-stage static smem (48 KB), 2 CTAs/SM, 1 sync/chunk.
#define ST 3
#define STAGE_B 16384       // A 8KB + B 8KB

__device__ __forceinline__ uint32_t swzo(int row, int kcol) {
    return (uint32_t)(row * 64 + ((((kcol >> 3) ^ ((row >> 1) & 3)) << 4)) + ((kcol & 7) << 1));
}

__global__ void __launch_bounds__(256, 2)
gemm_mma(uint32_t aPack, uint32_t bPack, int npass, int K,
         const float* __restrict__ bias, float* Cext, int cselv, int ldc,
         int relu, int conv)   // conv: 0 none, 1 also bf16->g_i0, 2 bf16 ONLY ->g_lb
{
    __shared__ __align__(1024) char smem[ST * STAGE_B];
    const uint32_t sb = smem_u32(smem);
    const int tid = threadIdx.x, lane = tid & 31, wid = tid >> 5;
    const int wm = wid & 1, wn = wid >> 1;          // warp grid 2(M) x 4(N)
    const int bn = blockIdx.x, bm = blockIdx.y;
    float* C = csel(cselv, Cext);

    const int kcp = K >> 5;
    const int NCH = npass * kcp;

    float acc[4][4][4];
    #pragma unroll
    for (int i = 0; i < 4; i++)
        #pragma unroll
        for (int j = 0; j < 4; j++)
            #pragma unroll
            for (int q = 0; q < 4; q++) acc[i][j][q] = 0.0f;

    auto load_chunk = [&](int ch, int buf) {
        const int p = ch / kcp, kc = ch % kcp;
        const __nv_bfloat16* A = bufsel((aPack >> (4 * p)) & 15) + (size_t)(bm * 128) * K + kc * 32;
        const __nv_bfloat16* B = bufsel((bPack >> (4 * p)) & 15) + (size_t)(bn * 128) * K + kc * 32;
        const uint32_t ab = sb + buf * STAGE_B;
        const uint32_t bb = ab + 8192;
        #pragma unroll
        for (int i = 0; i < 2; i++) {
            const int g = tid + i * 256, r = g >> 2, c = g & 3;
            const uint32_t so = swzo(r, c * 8);
            CPA16(ab + so, A + (size_t)r * K + c * 8);
            CPA16(bb + so, B + (size_t)r * K + c * 8);
        }
        CPA_COMMIT();
    };

    load_chunk(0, 0);
    if (NCH > 1) load_chunk(1, 1);

    const int a_r = wm * 64 + (lane & 15);                      // + mt*16
    const int a_kc = (lane >> 4) * 8;                           // + ks*16
    const int b_r = wn * 32 + (lane & 7) + ((lane >> 4) << 3);  // + q*16
    const int b_kc = ((lane >> 3) & 1) * 8;                     // + ks*16

    for (int c = 0; c < NCH; c++) {
        if (c + 1 < NCH) CPA_WAIT1();   // chunk c resident; c+1 may be in flight
        else CPA_WAIT0();
        __syncthreads();                // all warps past compute(c-1); chunk c visible
        if (c + 2 < NCH) load_chunk(c + 2, (c + 2) % ST);  // overwrites buf (c-1)%3: safe

        const uint32_t abase = sb + (c % ST) * STAGE_B;
        const uint32_t bbase = abase + 8192;
        #pragma unroll
        for (int ks = 0; ks < 2; ks++) {
            uint32_t af[4][4], bf[2][4];
            #pragma unroll
            for (int mt = 0; mt < 4; mt++)
                ldmx4(af[mt], abase + swzo(a_r + mt * 16, ks * 16 + a_kc));
            #pragma unroll
            for (int q = 0; q < 2; q++)
                ldmx4(bf[q], bbase + swzo(b_r + q * 16, ks * 16 + b_kc));
            #pragma unroll
            for (int mt = 0; mt < 4; mt++)
                #pragma unroll
                for (int nt = 0; nt < 4; nt++)
                    mma16816(acc[mt][nt], af[mt], &bf[nt >> 1][(nt & 1) * 2]);
        }
    }

    #pragma unroll
    for (int mt = 0; mt < 4; mt++) {
        const int r0 = bm * 128 + wm * 64 + mt * 16 + (lane >> 2);
        #pragma unroll
        for (int nt = 0; nt < 4; nt++) {
            const int col = bn * 128 + wn * 32 + nt * 8 + (lane & 3) * 2;
            const float bb0 = bias[col], bb1 = bias[col + 1];
            float v0 = acc[mt][nt][0] + bb0, v1 = acc[mt][nt][1] + bb1;
            float v2 = acc[mt][nt][2] + bb0, v3 = acc[mt][nt][3] + bb1;
            if (relu) {
                v0 = fmaxf(v0, 0.f); v1 = fmaxf(v1, 0.f);
                v2 = fmaxf(v2, 0.f); v3 = fmaxf(v3, 0.f);
            }
            if (conv != 2) {
                *(float2*)(C + (size_t)r0 * ldc + col) = make_float2(v0, v1);
                *(float2*)(C + (size_t)(r0 + 8) * ldc + col) = make_float2(v2, v3);
            }
            if (conv) {
                __nv_bfloat16* tb = (conv == 1) ? g_i0 : g_lb;
                *(__nv_bfloat162*)(tb + (size_t)r0 * ldc + col) =
                    __nv_bfloat162(__float2bfloat16(v0), __float2bfloat16(v1));
                *(__nv_bfloat162*)(tb + (size_t)(r0 + 8) * ldc + col) =
                    __nv_bfloat162(__float2bfloat16(v2), __float2bfloat16(v3));
            }
        }
    }
}

// ---------------- prep ----------------
__global__ void split_x2_kernel(const float* __restrict__ x) {
    size_t i = (size_t)blockIdx.x * blockDim.x + threadIdx.x;
    const size_t n = (size_t)NTOK * Hd;
    if (i >= n) return;
    float v = x[i];
    __nv_bfloat16 h0 = __float2bfloat16(v);
    g_xa0[i] = h0;
    g_xa1[i] = __float2bfloat16(v - __bfloat162float(h0));
}

__global__ void transpose_split(const float* __restrict__ W, int R, int C,
                                int s0, int s1, int wf) {
    __nv_bfloat16* T0 = bufselw(s0);
    __nv_bfloat16* T1 = (s1 >= 0) ? bufselw(s1) : nullptr;
    float* TF = wf ? g_w2tf : nullptr;

    __shared__ float t[32][33];
    const int bx = blockIdx.x * 32, by = blockIdx.y * 32;
    const int tx = threadIdx.x, ty = threadIdx.y;
    #pragma unroll
    for (int i = 0; i < 4; i++)
        t[ty + i * 8][tx] = W[(size_t)(by + ty + i * 8) * C + bx + tx];
    __syncthreads();
    #pragma unroll
    for (int i = 0; i < 4; i++) {
        const int c = bx + ty + i * 8, r = by + tx;
        const float v = t[tx][ty + i * 8];
        const size_t o = (size_t)c * R + r;
        __nv_bfloat16 h0 = __float2bfloat16(v);
        T0[o] = h0;
        if (T1) T1[o] = __float2bfloat16(v - __bfloat162float(h0));
        if (TF) TF[o] = v;
    }
}

// ---------------- reductions ----------------
template <int NT>
__device__ __forceinline__ float breduce(float v) {
    __shared__ float sh[NT];
    int tid = threadIdx.x;
    sh[tid] = v; __syncthreads();
    #pragma unroll
    for (int s = NT / 2; s > 0; s >>= 1) {
        if (tid < s) sh[tid] += sh[tid + s];
        __syncthreads();
    }
    float r = sh[0]; __syncthreads();
    return r;
}

__global__ void zero_usage_kernel() {
    int i = blockIdx.x * blockDim.x + threadIdx.x;
    if (i < Pd) g_usage[i] = 0.0f;
}

// ---------------- top-2: bf16 approx scan + exact fp32 recompute ------------
__global__ void __launch_bounds__(256)
topk_kernel(const float* __restrict__ pool, const float* __restrict__ temp_ptr,
            const float* __restrict__ b2)
{
    const int row = blockIdx.x, tid = threadIdx.x;
    const int wid = tid >> 5, lane = tid & 31;
    const __nv_bfloat16* lrow = g_lb + (size_t)row * Pd;
    float t = temp_ptr[0];
    t = fminf(fmaxf(t, 0.1f), 5.0f);
    const float it = 1.0f / t;

    float v1 = -INFINITY, v2 = -INFINITY;
    for (int j = tid * 2; j < Pd; j += 512) {
        __nv_bfloat162 p2 = *(const __nv_bfloat162*)(lrow + j);
        float va = fminf(fmaxf(__bfloat162float(p2.x) * it, -10.0f), 10.0f);
        float vb = fminf(fmaxf(__bfloat162float(p2.y) * it, -10.0f), 10.0f);
        float hi = fmaxf(va, vb), lo = fminf(va, vb);
        if (hi > v1) { v2 = fmaxf(v1, lo); v1 = hi; }
        else v2 = fmaxf(v2, hi);
    }
    __shared__ float s1[256], s2[256];
    s1[tid] = v1; s2[tid] = v2; __syncthreads();
    for (int s = 128; s > 0; s >>= 1) {
        if (tid < s) {
            float a1 = s1[tid], a2 = s2[tid], b1v = s1[tid + s], b2v = s2[tid + s];
            s1[tid] = fmaxf(a1, b1v);
            s2[tid] = fmaxf(fminf(a1, b1v), fmaxf(a2, b2v));
        }
        __syncthreads();
    }
    const float thr = s2[0] - 0.05f * it;

    __shared__ int cands[64];
    __shared__ int ncand;
    if (tid == 0) ncand = 0;
    __syncthreads();
    for (int j = tid * 2; j < Pd; j += 512) {
        __nv_bfloat162 p2 = *(const __nv_bfloat162*)(lrow + j);
        float va = fminf(fmaxf(__bfloat162float(p2.x) * it, -10.0f), 10.0f);
        float vb = fminf(fmaxf(__bfloat162float(p2.y) * it, -10.0f), 10.0f);
        if (va >= thr) { int p = atomicAdd(&ncand, 1); if (p < 64) cands[p] = j; }
        if (vb >= thr) { int p = atomicAdd(&ncand, 1); if (p < 64) cands[p] = j + 1; }
    }
    __syncthreads();
    const int nc = min(ncand, 64);

    __shared__ float exv[64];
    const float* irow = g_inter + (size_t)row * Id;
    for (int base = 0; base < nc; base += 8) {
        const int q = base + wid;
        if (q < nc) {
            const int j = cands[q];
            const float* wr = g_w2tf + (size_t)j * Id;
            float s = 0.0f;
            for (int k = lane; k < Id; k += 32) s += irow[k] * wr[k];
            #pragma unroll
            for (int o = 16; o > 0; o >>= 1) s += __shfl_down_sync(0xffffffffu, s, o);
            if (lane == 0) exv[q] = fminf(fmaxf((s + b2[j]) / t, -10.0f), 10.0f);
        }
    }
    __syncthreads();

    __shared__ float sw0, sw1;
    __shared__ int sj0, sj1;
    if (tid == 0) {
        float bv1 = -INFINITY, bv2 = -INFINITY;
        int bi1 = 0x7fffffff, bi2 = 0x7fffffff;
        for (int q = 0; q < nc; q++) {
            float v = exv[q]; int j = cands[q];
            if (v > bv1 || (v == bv1 && j < bi1)) {
                bv2 = bv1; bi2 = bi1; bv1 = v; bi1 = j;
            } else if (v > bv2 || (v == bv2 && j < bi2)) {
                bv2 = v; bi2 = j;
            }
        }
        float e = expf(bv2 - bv1), se = 1.0f + e;
        sw0 = 1.0f / se; sw1 = e / se; sj0 = bi1; sj1 = bi2;
        atomicAdd(&g_usage[bi1], sw0);
        atomicAdd(&g_usage[bi2], sw1);
    }
    __syncthreads();

    const float w0 = sw0, w1 = sw1;
    float4 a = ((const float4*)(pool + (size_t)sj0 * Dd))[tid];
    float4 b = ((const float4*)(pool + (size_t)sj1 * Dd))[tid];
    float ov[4] = { w0 * a.x + w1 * b.x, w0 * a.y + w1 * b.y,
                    w0 * a.z + w1 * b.z, w0 * a.w + w1 * b.w };
    const size_t off = (size_t)row * (2 * Dd) + Dd + tid * 4;
    #pragma unroll
    for (int q = 0; q < 4; q++) {
        __nv_bfloat16 h0 = __float2bfloat16(ov[q]);
        g_ca0[off + q] = h0;
        g_ca1[off + q] = __float2bfloat16(ov[q] - __bfloat162float(h0));
    }
}

// ---------------- layernorm -> combined[:, 0:D] splits ----------------
__global__ void __launch_bounds__(256)
ln_kernel(const float* __restrict__ gamma, const float* __restrict__ beta)
{
    const int row = blockIdx.x, tid = threadIdx.x;
    float4 v = ((const float4*)(g_proj + (size_t)row * Dd))[tid];
    float s = v.x + v.y + v.z + v.w;
    s = breduce<256>(s);
    const float mean = s * (1.0f / Dd);
    float d0 = v.x - mean, d1 = v.y - mean, d2 = v.z - mean, d3 = v.w - mean;
    float q = d0 * d0 + d1 * d1 + d2 * d2 + d3 * d3;
    q = breduce<256>(q);
    const float rs = rsqrtf(q * (1.0f / Dd) + 1e-5f);
    float4 g = ((const float4*)gamma)[tid], b = ((const float4*)beta)[tid];
    float ov[4] = { d0 * rs * g.x + b.x, d1 * rs * g.y + b.y,
                    d2 * rs * g.z + b.z, d3 * rs * g.w + b.w };
    const size_t off = (size_t)row * (2 * Dd) + tid * 4;
    #pragma unroll
    for (int k = 0; k < 4; k++) {
        __nv_bfloat16 h0 = __float2bfloat16(ov[k]);
        g_ca0[off + k] = h0;
        g_ca1[off + k] = __float2bfloat16(ov[k] - __bfloat162float(h0));
    }
}

// ---------------- diversity loss ----------------
__global__ void __launch_bounds__(512)
loss_kernel(float* __restrict__ out, int do_write)
{
    const int tid = threadIdx.x;
    float s = 0.0f;
    for (int j = tid; j < Pd; j += 512) s += g_usage[j];
    s = breduce<512>(s);
    const float denom = s + 1e-8f, uni = 1.0f / Pd;
    float q = 0.0f;
    for (int j = tid; j < Pd; j += 512) {
        float d = g_usage[j] / denom - uni;
        q += d * d;
    }
    q = breduce<512>(q);
    if (tid == 0 && do_write) out[0] = (q / Pd) * 0.01f;
}

// ---------------- launch ----------------
extern "C" void kernel_launch(void* const* d_in, const int* in_sizes, int n_in,
                              void* d_out, int out_size)
{
    const int o = (n_in >= 14) ? 1 : 0;
    const float* x     = (const float*)d_in[0];
    const float* pool  = (const float*)d_in[1];
    const float* w1    = (const float*)d_in[2 + o];
    const float* b1    = (const float*)d_in[3 + o];
    const float* w2    = (const float*)d_in[4 + o];
    const float* b2    = (const float*)d_in[5 + o];
    const float* temp  = (const float*)d_in[6 + o];
    const float* wp    = (const float*)d_in[7 + o];
    const float* bp    = (const float*)d_in[8 + o];
    const float* gamma = (const float*)d_in[9 + o];
    const float* beta  = (const float*)d_in[10 + o];
    const float* wm    = (const float*)d_in[11 + o];
    const float* bm    = (const float*)d_in[12 + o];
    float* out = (float*)d_out;

    split_x2_kernel<<<((size_t)NTOK * Hd + 255) / 256, 256>>>(x);
    transpose_split<<<dim3(Id / 32, Hd / 32), dim3(32, 8)>>>(w1, Hd, Id, 3, 4, 0);
    transpose_split<<<dim3(Pd / 32, Id / 32), dim3(32, 8)>>>(w2, Id, Pd, 7, -1, 1);
    transpose_split<<<dim3(Dd / 32, Hd / 32), dim3(32, 8)>>>(wp, Hd, Dd, 8, 9, 0);
    transpose_split<<<dim3(Dd / 32, (2 * Dd) / 32), dim3(32, 8)>>>(wm, 2 * Dd, Dd, 12, 13, 0);
    zero_usage_kernel<<<Pd / 256, 256>>>();

    // G1: inter = relu(x@w1+b1); 3-pass; fp32 + bf16 copy
    gemm_mma<<<dim3(Id / 128, NTOK / 128), 256>>>(
        0x100u, 0x343u, 3, Hd, b1, nullptr, 0, Id, 1, 1);

    // G2: logits = inter@w2+b2; 1-pass bf16 -> g_lb only
    gemm_mma<<<dim3(Pd / 128, NTOK / 128), 256>>>(
        0x6u, 0x7u, 1, Id, b2, nullptr, 9, Pd, 0, 2);

    topk_kernel<<<NTOK, 256>>>(pool, temp, b2);

    // G3: proj = x@wp+bp; 3-pass
    gemm_mma<<<dim3(Dd / 128, NTOK / 128), 256>>>(
        0x100u, 0x898u, 3, Hd, bp, nullptr, 2, Dd, 0, 0);

    ln_kernel<<<NTOK, 256>>>(gamma, beta);

    // G4: out = combined@wm+bm; 3-pass
    gemm_mma<<<dim3(Dd / 128, NTOK / 128), 256>>>(
        0xBAAu, 0xCDCu, 3, 2 * Dd, bm, out, 9, Dd, 0, 0);

    const long long tsz = (long long)NTOK * Dd;
    loss_kernel<<<1, 512>>>(out + tsz, ((long long)out_size > tsz) ? 1 : 0);
}

// round 11
// speedup vs baseline: 1.5139x; 1.2164x over previous
#include <cuda_runtime.h>
#include <cuda_fp16.h>
#include <cstdint>
#include <cstddef>
#include <math.h>

#define NTOK 8192
#define Hd 2048
#define Id 1024
#define Pd 4096
#define Dd 1024

// ---------------- static device scratch (fp16 splits) ----------------
__device__ __half g_xa0[(size_t)NTOK * Hd];
__device__ __half g_xa1[(size_t)NTOK * Hd];
__device__ __half g_w1t0[(size_t)Id * Hd];
__device__ __half g_w1t1[(size_t)Id * Hd];
__device__ __half g_i0[(size_t)NTOK * Id];
__device__ __half g_w2t0[(size_t)Pd * Id];
__device__ float  g_w2tf[(size_t)Pd * Id];
__device__ __half g_wpt0[(size_t)Dd * Hd];
__device__ __half g_ca0[(size_t)NTOK * 2 * Dd];
__device__ __half g_ca1[(size_t)NTOK * 2 * Dd];
__device__ __half g_wmt0[(size_t)Dd * 2 * Dd];
__device__ __half g_lb[(size_t)NTOK * Pd];      // fp16 logits
__device__ float  g_inter[(size_t)NTOK * Id];
__device__ float  g_proj[(size_t)NTOK * Dd];
__device__ float  g_usage[Pd];

__device__ __forceinline__ __half* bufselw(int s) {
    switch (s) {
        case 0:  return g_xa0;  case 1:  return g_xa1;
        case 3:  return g_w1t0; case 4:  return g_w1t1;
        case 6:  return g_i0;   case 7:  return g_w2t0;
        case 8:  return g_wpt0;
        case 10: return g_ca0;  case 11: return g_ca1;
        default: return g_wmt0;
    }
}
__device__ __forceinline__ const __half* bufsel(int s) { return bufselw(s); }
__device__ __forceinline__ float* csel(int s, float* ext) {
    switch (s) {
        case 0: return g_inter;
        case 2: return g_proj;
        default: return ext;
    }
}

// ---------------- PTX helpers ----------------
__device__ __forceinline__ uint32_t smem_u32(const void* p) {
    uint32_t a;
    asm("{ .reg .u64 t; cvta.to.shared.u64 t, %1; cvt.u32.u64 %0, t; }" : "=r"(a) : "l"(p));
    return a;
}
#define CPA16(d, s) asm volatile("cp.async.cg.shared.global [%0], [%1], 16;" :: "r"(d), "l"(s) : "memory")
#define CPA_COMMIT() asm volatile("cp.async.commit_group;" ::: "memory")
#define CPA_WAIT2() asm volatile("cp.async.wait_group 2;" ::: "memory")
#define CPA_WAIT1() asm volatile("cp.async.wait_group 1;" ::: "memory")
#define CPA_WAIT0() asm volatile("cp.async.wait_group 0;" ::: "memory")

__device__ __forceinline__ void ldmx4(uint32_t* r, uint32_t addr) {
    asm volatile("ldmatrix.sync.aligned.m8n8.x4.shared.b16 {%0,%1,%2,%3}, [%4];"
                 : "=r"(r[0]), "=r"(r[1]), "=r"(r[2]), "=r"(r[3]) : "r"(addr));
}
__device__ __forceinline__ void mma16816(float* d, const uint32_t* a, const uint32_t* b) {
    asm volatile("mma.sync.aligned.m16n8k16.row.col.f32.f16.f16.f32 "
                 "{%0,%1,%2,%3}, {%4,%5,%6,%7}, {%8,%9}, {%0,%1,%2,%3};"
                 : "+f"(d[0]), "+f"(d[1]), "+f"(d[2]), "+f"(d[3])
                 : "r"(a[0]), "r"(a[1]), "r"(a[2]), "r"(a[3]), "r"(b[0]), "r"(b[1]));
}

// ---------------- HMMA GEMM: D[M,N] = sum_p A_p @ B_p^T + bias --------------
// Tile 128x128, BK=32, 3-stage static smem (48 KB), 2 CTAs/SM. R8 loop verbatim.
#define ST 3
#define STAGE_B 16384       // A 8KB + B 8KB

__device__ __forceinline__ uint32_t swzo(int row, int kcol) {
    return (uint32_t)(row * 64 + ((((kcol >> 3) ^ ((row >> 1) & 3)) << 4)) + ((kcol & 7) << 1));
}

__global__ void __launch_bounds__(256, 2)
gemm_mma(uint32_t aPack, uint32_t bPack, int npass, int K,
         const float* __restrict__ bias, float* Cext, int cselv, int ldc,
         int relu, int conv)   // conv: 0 none, 1 also fp16->g_i0, 2 fp16 ONLY ->g_lb
{
    __shared__ __align__(1024) char smem[ST * STAGE_B];
    const uint32_t sb = smem_u32(smem);
    const int tid = threadIdx.x, lane = tid & 31, wid = tid >> 5;
    const int wm = wid & 1, wn = wid >> 1;          // warp grid 2(M) x 4(N)
    const int bn = blockIdx.x, bm = blockIdx.y;
    float* C = csel(cselv, Cext);

    const int kcp = K >> 5;
    const int NCH = npass * kcp;

    float acc[4][4][4];
    #pragma unroll
    for (int i = 0; i < 4; i++)
        #pragma unroll
        for (int j = 0; j < 4; j++)
            #pragma unroll
            for (int q = 0; q < 4; q++) acc[i][j][q] = 0.0f;

    auto load_chunk = [&](int ch, int buf) {
        const int p = ch / kcp, kc = ch % kcp;
        const __half* A = bufsel((aPack >> (4 * p)) & 15) + (size_t)(bm * 128) * K + kc * 32;
        const __half* B = bufsel((bPack >> (4 * p)) & 15) + (size_t)(bn * 128) * K + kc * 32;
        const uint32_t ab = sb + buf * STAGE_B;
        const uint32_t bb = ab + 8192;
        #pragma unroll
        for (int i = 0; i < 2; i++) {
            const int g = tid + i * 256, r = g >> 2, c = g & 3;
            const uint32_t so = swzo(r, c * 8);
            CPA16(ab + so, A + (size_t)r * K + c * 8);
            CPA16(bb + so, B + (size_t)r * K + c * 8);
        }
        CPA_COMMIT();
    };

    load_chunk(0, 0);
    if (NCH > 1) load_chunk(1, 1);

    const int a_r = wm * 64 + (lane & 15);                      // + mt*16
    const int a_kc = (lane >> 4) * 8;                           // + ks*16
    const int b_r = wn * 32 + (lane & 7) + ((lane >> 4) << 3);  // + q*16
    const int b_kc = ((lane >> 3) & 1) * 8;                     // + ks*16

    for (int c = 0; c < NCH; c++) {
        if (c + 2 < NCH) { load_chunk(c + 2, (c + 2) % ST); CPA_WAIT2(); }
        else if (c + 1 < NCH) CPA_WAIT1();
        else CPA_WAIT0();
        __syncthreads();

        const uint32_t abase = sb + (c % ST) * STAGE_B;
        const uint32_t bbase = abase + 8192;
        #pragma unroll
        for (int ks = 0; ks < 2; ks++) {
            uint32_t af[4][4], bf[2][4];
            #pragma unroll
            for (int mt = 0; mt < 4; mt++)
                ldmx4(af[mt], abase + swzo(a_r + mt * 16, ks * 16 + a_kc));
            #pragma unroll
            for (int q = 0; q < 2; q++)
                ldmx4(bf[q], bbase + swzo(b_r + q * 16, ks * 16 + b_kc));
            #pragma unroll
            for (int mt = 0; mt < 4; mt++)
                #pragma unroll
                for (int nt = 0; nt < 4; nt++)
                    mma16816(acc[mt][nt], af[mt], &bf[nt >> 1][(nt & 1) * 2]);
        }
        __syncthreads();
    }

    #pragma unroll
    for (int mt = 0; mt < 4; mt++) {
        const int r0 = bm * 128 + wm * 64 + mt * 16 + (lane >> 2);
        #pragma unroll
        for (int nt = 0; nt < 4; nt++) {
            const int col = bn * 128 + wn * 32 + nt * 8 + (lane & 3) * 2;
            const float bb0 = bias[col], bb1 = bias[col + 1];
            float v0 = acc[mt][nt][0] + bb0, v1 = acc[mt][nt][1] + bb1;
            float v2 = acc[mt][nt][2] + bb0, v3 = acc[mt][nt][3] + bb1;
            if (relu) {
                v0 = fmaxf(v0, 0.f); v1 = fmaxf(v1, 0.f);
                v2 = fmaxf(v2, 0.f); v3 = fmaxf(v3, 0.f);
            }
            if (conv != 2) {
                *(float2*)(C + (size_t)r0 * ldc + col) = make_float2(v0, v1);
                *(float2*)(C + (size_t)(r0 + 8) * ldc + col) = make_float2(v2, v3);
            }
            if (conv) {
                __half* tb = (conv == 1) ? g_i0 : g_lb;
                *(__half2*)(tb + (size_t)r0 * ldc + col) =
                    __halves2half2(__float2half(v0), __float2half(v1));
                *(__half2*)(tb + (size_t)(r0 + 8) * ldc + col) =
                    __halves2half2(__float2half(v2), __float2half(v3));
            }
        }
    }
}

// ---------------- prep ----------------
__global__ void split_x2_kernel(const float* __restrict__ x) {
    size_t i = (size_t)blockIdx.x * blockDim.x + threadIdx.x;
    const size_t n = (size_t)NTOK * Hd;
    if (i >= n) return;
    float v = x[i];
    __half h0 = __float2half(v);
    g_xa0[i] = h0;
    g_xa1[i] = __float2half(v - __half2float(h0));
}

__global__ void transpose_split(const float* __restrict__ W, int R, int C,
                                int s0, int s1, int wf) {
    __half* T0 = bufselw(s0);
    __half* T1 = (s1 >= 0) ? bufselw(s1) : nullptr;
    float* TF = wf ? g_w2tf : nullptr;

    __shared__ float t[32][33];
    const int bx = blockIdx.x * 32, by = blockIdx.y * 32;
    const int tx = threadIdx.x, ty = threadIdx.y;
    #pragma unroll
    for (int i = 0; i < 4; i++)
        t[ty + i * 8][tx] = W[(size_t)(by + ty + i * 8) * C + bx + tx];
    __syncthreads();
    #pragma unroll
    for (int i = 0; i < 4; i++) {
        const int c = bx + ty + i * 8, r = by + tx;
        const float v = t[tx][ty + i * 8];
        const size_t o = (size_t)c * R + r;
        __half h0 = __float2half(v);
        T0[o] = h0;
        if (T1) T1[o] = __float2half(v - __half2float(h0));
        if (TF) TF[o] = v;
    }
}

// ---------------- reductions ----------------
template <int NT>
__device__ __forceinline__ float breduce(float v) {
    __shared__ float sh[NT];
    int tid = threadIdx.x;
    sh[tid] = v; __syncthreads();
    #pragma unroll
    for (int s = NT / 2; s > 0; s >>= 1) {
        if (tid < s) sh[tid] += sh[tid + s];
        __syncthreads();
    }
    float r = sh[0]; __syncthreads();
    return r;
}

__global__ void zero_usage_kernel() {
    int i = blockIdx.x * blockDim.x + threadIdx.x;
    if (i < Pd) g_usage[i] = 0.0f;
}

// ---------------- top-2: fp16 approx scan + exact fp32 recompute ------------
__global__ void __launch_bounds__(256)
topk_kernel(const float* __restrict__ pool, const float* __restrict__ temp_ptr,
            const float* __restrict__ b2)
{
    const int row = blockIdx.x, tid = threadIdx.x;
    const int wid = tid >> 5, lane = tid & 31;
    const __half* lrow = g_lb + (size_t)row * Pd;
    float t = temp_ptr[0];
    t = fminf(fmaxf(t, 0.1f), 5.0f);
    const float it = 1.0f / t;

    float v1 = -INFINITY, v2 = -INFINITY;
    for (int j = tid * 2; j < Pd; j += 512) {
        __half2 p2 = *(const __half2*)(lrow + j);
        float va = fminf(fmaxf(__low2float(p2) * it, -10.0f), 10.0f);
        float vb = fminf(fmaxf(__high2float(p2) * it, -10.0f), 10.0f);
        float hi = fmaxf(va, vb), lo = fminf(va, vb);
        if (hi > v1) { v2 = fmaxf(v1, lo); v1 = hi; }
        else v2 = fmaxf(v2, hi);
    }
    __shared__ float s1[256], s2[256];
    s1[tid] = v1; s2[tid] = v2; __syncthreads();
    for (int s = 128; s > 0; s >>= 1) {
        if (tid < s) {
            float a1 = s1[tid], a2 = s2[tid], b1v = s1[tid + s], b2v = s2[tid + s];
            s1[tid] = fmaxf(a1, b1v);
            s2[tid] = fmaxf(fminf(a1, b1v), fmaxf(a2, b2v));
        }
        __syncthreads();
    }
    // fp16 1-pass mma err + fp16 storage quant: raw <= ~2e-3; margin 0.02 >= 10x
    const float thr = s2[0] - 0.02f * it;

    __shared__ int cands[64];
    __shared__ int ncand;
    if (tid == 0) ncand = 0;
    __syncthreads();
    for (int j = tid * 2; j < Pd; j += 512) {
        __half2 p2 = *(const __half2*)(lrow + j);
        float va = fminf(fmaxf(__low2float(p2) * it, -10.0f), 10.0f);
        float vb = fminf(fmaxf(__high2float(p2) * it, -10.0f), 10.0f);
        if (va >= thr) { int p = atomicAdd(&ncand, 1); if (p < 64) cands[p] = j; }
        if (vb >= thr) { int p = atomicAdd(&ncand, 1); if (p < 64) cands[p] = j + 1; }
    }
    __syncthreads();
    const int nc = min(ncand, 64);

    __shared__ float exv[64];
    const float* irow = g_inter + (size_t)row * Id;
    for (int base = 0; base < nc; base += 8) {
        const int q = base + wid;
        if (q < nc) {
            const int j = cands[q];
            const float* wr = g_w2tf + (size_t)j * Id;
            float s = 0.0f;
            for (int k = lane; k < Id; k += 32) s += irow[k] * wr[k];
            #pragma unroll
            for (int o = 16; o > 0; o >>= 1) s += __shfl_down_sync(0xffffffffu, s, o);
            if (lane == 0) exv[q] = fminf(fmaxf((s + b2[j]) / t, -10.0f), 10.0f);
        }
    }
    __syncthreads();

    __shared__ float sw0, sw1;
    __shared__ int sj0, sj1;
    if (tid == 0) {
        float bv1 = -INFINITY, bv2 = -INFINITY;
        int bi1 = 0x7fffffff, bi2 = 0x7fffffff;
        for (int q = 0; q < nc; q++) {
            float v = exv[q]; int j = cands[q];
            if (v > bv1 || (v == bv1 && j < bi1)) {
                bv2 = bv1; bi2 = bi1; bv1 = v; bi1 = j;
            } else if (v > bv2 || (v == bv2 && j < bi2)) {
                bv2 = v; bi2 = j;
            }
        }
        float e = expf(bv2 - bv1), se = 1.0f + e;
        sw0 = 1.0f / se; sw1 = e / se; sj0 = bi1; sj1 = bi2;
        atomicAdd(&g_usage[bi1], sw0);
        atomicAdd(&g_usage[bi2], sw1);
    }
    __syncthreads();

    const float w0 = sw0, w1 = sw1;
    float4 a = ((const float4*)(pool + (size_t)sj0 * Dd))[tid];
    float4 b = ((const float4*)(pool + (size_t)sj1 * Dd))[tid];
    float ov[4] = { w0 * a.x + w1 * b.x, w0 * a.y + w1 * b.y,
                    w0 * a.z + w1 * b.z, w0 * a.w + w1 * b.w };
    const size_t off = (size_t)row * (2 * Dd) + Dd + tid * 4;
    #pragma unroll
    for (int q = 0; q < 4; q++) {
        __half h0 = __float2half(ov[q]);
        g_ca0[off + q] = h0;
        g_ca1[off + q] = __float2half(ov[q] - __half2float(h0));
    }
}

// ---------------- layernorm -> combined[:, 0:D] splits ----------------
__global__ void __launch_bounds__(256)
ln_kernel(const float* __restrict__ gamma, const float* __restrict__ beta)
{
    const int row = blockIdx.x, tid = threadIdx.x;
    float4 v = ((const float4*)(g_proj + (size_t)row * Dd))[tid];
    float s = v.x + v.y + v.z + v.w;
    s = breduce<256>(s);
    const float mean = s * (1.0f / Dd);
    float d0 = v.x - mean, d1 = v.y - mean, d2 = v.z - mean, d3 = v.w - mean;
    float q = d0 * d0 + d1 * d1 + d2 * d2 + d3 * d3;
    q = breduce<256>(q);
    const float rs = rsqrtf(q * (1.0f / Dd) + 1e-5f);
    float4 g = ((const float4*)gamma)[tid], b = ((const float4*)beta)[tid];
    float ov[4] = { d0 * rs * g.x + b.x, d1 * rs * g.y + b.y,
                    d2 * rs * g.z + b.z, d3 * rs * g.w + b.w };
    const size_t off = (size_t)row * (2 * Dd) + tid * 4;
    #pragma unroll
    for (int k = 0; k < 4; k++) {
        __half h0 = __float2half(ov[k]);
        g_ca0[off + k] = h0;
        g_ca1[off + k] = __float2half(ov[k] - __half2float(h0));
    }
}

// ---------------- diversity loss ----------------
__global__ void __launch_bounds__(512)
loss_kernel(float* __restrict__ out, int do_write)
{
    const int tid = threadIdx.x;
    float s = 0.0f;
    for (int j = tid; j < Pd; j += 512) s += g_usage[j];
    s = breduce<512>(s);
    const float denom = s + 1e-8f, uni = 1.0f / Pd;
    float q = 0.0f;
    for (int j = tid; j < Pd; j += 512) {
        float d = g_usage[j] / denom - uni;
        q += d * d;
    }
    q = breduce<512>(q);
    if (tid == 0 && do_write) out[0] = (q / Pd) * 0.01f;
}

// ---------------- launch ----------------
extern "C" void kernel_launch(void* const* d_in, const int* in_sizes, int n_in,
                              void* d_out, int out_size)
{
    const int o = (n_in >= 14) ? 1 : 0;
    const float* x     = (const float*)d_in[0];
    const float* pool  = (const float*)d_in[1];
    const float* w1    = (const float*)d_in[2 + o];
    const float* b1    = (const float*)d_in[3 + o];
    const float* w2    = (const float*)d_in[4 + o];
    const float* b2    = (const float*)d_in[5 + o];
    const float* temp  = (const float*)d_in[6 + o];
    const float* wp    = (const float*)d_in[7 + o];
    const float* bp    = (const float*)d_in[8 + o];
    const float* gamma = (const float*)d_in[9 + o];
    const float* beta  = (const float*)d_in[10 + o];
    const float* wm    = (const float*)d_in[11 + o];
    const float* bm    = (const float*)d_in[12 + o];
    float* out = (float*)d_out;

    split_x2_kernel<<<((size_t)NTOK * Hd + 255) / 256, 256>>>(x);
    transpose_split<<<dim3(Id / 32, Hd / 32), dim3(32, 8)>>>(w1, Hd, Id, 3, 4, 0);
    transpose_split<<<dim3(Pd / 32, Id / 32), dim3(32, 8)>>>(w2, Id, Pd, 7, -1, 1);
    transpose_split<<<dim3(Dd / 32, Hd / 32), dim3(32, 8)>>>(wp, Hd, Dd, 8, -1, 0);
    transpose_split<<<dim3(Dd / 32, (2 * Dd) / 32), dim3(32, 8)>>>(wm, 2 * Dd, Dd, 12, -1, 0);
    zero_usage_kernel<<<Pd / 256, 256>>>();

    // G1: inter = relu(x@w1+b1); 3-pass fp16 (x0w0, x0w1, x1w0); fp32 + fp16 copy
    gemm_mma<<<dim3(Id / 128, NTOK / 128), 256>>>(
        0x100u, 0x343u, 3, Hd, b1, nullptr, 0, Id, 1, 1);

    // G2: logits = inter@w2+b2; 1-pass fp16 -> g_lb only
    gemm_mma<<<dim3(Pd / 128, NTOK / 128), 256>>>(
        0x6u, 0x7u, 1, Id, b2, nullptr, 9, Pd, 0, 2);

    topk_kernel<<<NTOK, 256>>>(pool, temp, b2);

    // G3: proj = x@wp+bp; 2-pass fp16 (x0·wp0, x1·wp0)
    gemm_mma<<<dim3(Dd / 128, NTOK / 128), 256>>>(
        0x10u, 0x88u, 2, Hd, bp, nullptr, 2, Dd, 0, 0);

    ln_kernel<<<NTOK, 256>>>(gamma, beta);

    // G4: out = combined@wm+bm; 2-pass fp16 (c0·m0, c1·m0)
    gemm_mma<<<dim3(Dd / 128, NTOK / 128), 256>>>(
        0xBAu, 0xCCu, 2, 2 * Dd, bm, out, 9, Dd, 0, 0);

    const long long tsz = (long long)NTOK * Dd;
    loss_kernel<<<1, 512>>>(out + tsz, ((long long)out_size > tsz) ? 1 : 0);
}